// round 1
// baseline (speedup 1.0000x reference)
#include <cuda_runtime.h>
#include <math.h>

// Problem dims
#define BATCH 8192
#define DHALF 1024
#define HID   4096
#define XCOLS 2048   // D1 + D2

// Scratch (allocation-free rule: device globals)
__device__ float g_hidden[(size_t)BATCH * HID];   // 128 MB
__device__ float g_s[(size_t)BATCH * DHALF];      // 32 MB
__device__ float g_t[(size_t)BATCH * DHALF];      // 32 MB

// ---------------------------------------------------------------------------
// Classic 128x128x8 register-tiled SGEMM: C[M,N] = op(A[M,K] @ W[K,N] + bias)
// A row-major with leading dim lda; W row-major (K x N); C row-major ldc.
// M=8192 always; K,N multiples of 8/128. op = ReLU if RELU.
// ---------------------------------------------------------------------------
template<bool RELU>
__global__ __launch_bounds__(256, 2)
void sgemm_bias(const float* __restrict__ A, int lda,
                const float* __restrict__ W,
                const float* __restrict__ bias,
                float* __restrict__ C, int ldc,
                int K, int N)
{
    __shared__ float As[8][128];
    __shared__ float Bs[8][128];

    const int tid = threadIdx.x;
    const int tx  = tid & 15;        // 0..15 -> n sub-tile
    const int ty  = tid >> 4;        // 0..15 -> m sub-tile
    const int mBase = blockIdx.y * 128;
    const int nBase = blockIdx.x * 128;

    // A-tile load mapping: 128 rows x 8 cols = 256 float4 (one per thread)
    const int ar = tid >> 1;             // 0..127
    const int ac = (tid & 1) * 4;        // 0 or 4
    // B-tile load mapping: 8 rows x 128 cols
    const int br = tid >> 5;             // 0..7
    const int bc = (tid & 31) * 4;       // 0..124

    const float* Aptr = A + (size_t)(mBase + ar) * lda + ac;
    const float* Wptr = W + (size_t)br * N + nBase + bc;

    float acc[8][8];
    #pragma unroll
    for (int i = 0; i < 8; ++i)
        #pragma unroll
        for (int j = 0; j < 8; ++j) acc[i][j] = 0.0f;

    for (int k0 = 0; k0 < K; k0 += 8) {
        float4 av = *reinterpret_cast<const float4*>(Aptr + k0);
        float4 bv = *reinterpret_cast<const float4*>(Wptr + (size_t)k0 * N);

        As[ac + 0][ar] = av.x;
        As[ac + 1][ar] = av.y;
        As[ac + 2][ar] = av.z;
        As[ac + 3][ar] = av.w;
        *reinterpret_cast<float4*>(&Bs[br][bc]) = bv;
        __syncthreads();

        #pragma unroll
        for (int k = 0; k < 8; ++k) {
            float a[8], b[8];
            *reinterpret_cast<float4*>(&a[0]) = *reinterpret_cast<const float4*>(&As[k][ty * 8]);
            *reinterpret_cast<float4*>(&a[4]) = *reinterpret_cast<const float4*>(&As[k][ty * 8 + 4]);
            *reinterpret_cast<float4*>(&b[0]) = *reinterpret_cast<const float4*>(&Bs[k][tx * 8]);
            *reinterpret_cast<float4*>(&b[4]) = *reinterpret_cast<const float4*>(&Bs[k][tx * 8 + 4]);
            #pragma unroll
            for (int i = 0; i < 8; ++i)
                #pragma unroll
                for (int j = 0; j < 8; ++j)
                    acc[i][j] = fmaf(a[i], b[j], acc[i][j]);
        }
        __syncthreads();
    }

    // Epilogue: bias (+ ReLU), vectorized stores
    const int nCol = nBase + tx * 8;
    float bvals[8];
    *reinterpret_cast<float4*>(&bvals[0]) = *reinterpret_cast<const float4*>(&bias[nCol]);
    *reinterpret_cast<float4*>(&bvals[4]) = *reinterpret_cast<const float4*>(&bias[nCol + 4]);

    #pragma unroll
    for (int i = 0; i < 8; ++i) {
        const int m = mBase + ty * 8 + i;
        float4 o0, o1;
        o0.x = acc[i][0] + bvals[0];
        o0.y = acc[i][1] + bvals[1];
        o0.z = acc[i][2] + bvals[2];
        o0.w = acc[i][3] + bvals[3];
        o1.x = acc[i][4] + bvals[4];
        o1.y = acc[i][5] + bvals[5];
        o1.z = acc[i][6] + bvals[6];
        o1.w = acc[i][7] + bvals[7];
        if (RELU) {
            o0.x = fmaxf(o0.x, 0.0f); o0.y = fmaxf(o0.y, 0.0f);
            o0.z = fmaxf(o0.z, 0.0f); o0.w = fmaxf(o0.w, 0.0f);
            o1.x = fmaxf(o1.x, 0.0f); o1.y = fmaxf(o1.y, 0.0f);
            o1.z = fmaxf(o1.z, 0.0f); o1.w = fmaxf(o1.w, 0.0f);
        }
        *reinterpret_cast<float4*>(&C[(size_t)m * ldc + nCol])     = o0;
        *reinterpret_cast<float4*>(&C[(size_t)m * ldc + nCol + 4]) = o1;
    }
}

// ---------------------------------------------------------------------------
// Fused coupling epilogue:
//   s   = tanh(spre)            (SCALE_LIMIT = 1.0)
//   yout = xin * exp(s) + tval
//   logdet[m] (=/+=) sum_j s[m,j]
// One block per row (m), 256 threads x float4 = 1024 cols.
// ---------------------------------------------------------------------------
__global__ __launch_bounds__(256)
void ew_couple(const float* __restrict__ x,     // full x, 2048 cols
               const float* __restrict__ spre,  // BATCH x 1024
               const float* __restrict__ tval,  // BATCH x 1024
               float* __restrict__ y,           // d_out base (stride 2048)
               float* __restrict__ logdet,      // BATCH
               int xColOff, int yColOff, int addLogdet)
{
    const int m = blockIdx.x;
    const int j = threadIdx.x * 4;

    float4 sp = *reinterpret_cast<const float4*>(&spre[(size_t)m * DHALF + j]);
    float4 tv = *reinterpret_cast<const float4*>(&tval[(size_t)m * DHALF + j]);
    float4 xv = *reinterpret_cast<const float4*>(&x[(size_t)m * XCOLS + xColOff + j]);

    float s0 = tanhf(sp.x), s1 = tanhf(sp.y), s2 = tanhf(sp.z), s3 = tanhf(sp.w);

    float4 o;
    o.x = xv.x * expf(s0) + tv.x;
    o.y = xv.y * expf(s1) + tv.y;
    o.z = xv.z * expf(s2) + tv.z;
    o.w = xv.w * expf(s3) + tv.w;
    *reinterpret_cast<float4*>(&y[(size_t)m * XCOLS + yColOff + j]) = o;

    float lsum = s0 + s1 + s2 + s3;
    #pragma unroll
    for (int off = 16; off > 0; off >>= 1)
        lsum += __shfl_xor_sync(0xFFFFFFFFu, lsum, off);

    __shared__ float wsum[8];
    if ((threadIdx.x & 31) == 0) wsum[threadIdx.x >> 5] = lsum;
    __syncthreads();
    if (threadIdx.x == 0) {
        float tot = 0.0f;
        #pragma unroll
        for (int w = 0; w < 8; ++w) tot += wsum[w];
        if (addLogdet) logdet[m] += tot;
        else           logdet[m]  = tot;
    }
}

// ---------------------------------------------------------------------------
extern "C" void kernel_launch(void* const* d_in, const int* in_sizes, int n_in,
                              void* d_out, int out_size)
{
    (void)in_sizes; (void)n_in; (void)out_size;

    const float* x     = (const float*)d_in[0];
    const float* s1_W1 = (const float*)d_in[1];
    const float* s1_b1 = (const float*)d_in[2];
    const float* s1_W2 = (const float*)d_in[3];
    const float* s1_b2 = (const float*)d_in[4];
    const float* t1_W1 = (const float*)d_in[5];
    const float* t1_b1 = (const float*)d_in[6];
    const float* t1_W2 = (const float*)d_in[7];
    const float* t1_b2 = (const float*)d_in[8];
    const float* s2_W1 = (const float*)d_in[9];
    const float* s2_b1 = (const float*)d_in[10];
    const float* s2_W2 = (const float*)d_in[11];
    const float* s2_b2 = (const float*)d_in[12];
    const float* t2_W1 = (const float*)d_in[13];
    const float* t2_b1 = (const float*)d_in[14];
    const float* t2_W2 = (const float*)d_in[15];
    const float* t2_b2 = (const float*)d_in[16];

    float* y      = (float*)d_out;                         // BATCH x 2048
    float* logdet = y + (size_t)BATCH * XCOLS;             // BATCH

    float *h, *sbuf, *tbuf;
    cudaGetSymbolAddress((void**)&h,    g_hidden);
    cudaGetSymbolAddress((void**)&sbuf, g_s);
    cudaGetSymbolAddress((void**)&tbuf, g_t);

    const float* x2 = x + DHALF;   // x[:, 1024:], lda = 2048

    dim3 blk(256);
    dim3 gridH(HID / 128,   BATCH / 128);  // N=4096 GEMMs
    dim3 gridD(DHALF / 128, BATCH / 128);  // N=1024 GEMMs

    // --- Half 1: s2v = tanh(mlp_s1(x2)), t2v = mlp_t1(x2), y1 ---
    sgemm_bias<true ><<<gridH, blk>>>(x2, XCOLS, s1_W1, s1_b1, h,    HID,   DHALF, HID);
    sgemm_bias<false><<<gridD, blk>>>(h,  HID,   s1_W2, s1_b2, sbuf, DHALF, HID,   DHALF);
    sgemm_bias<true ><<<gridH, blk>>>(x2, XCOLS, t1_W1, t1_b1, h,    HID,   DHALF, HID);
    sgemm_bias<false><<<gridD, blk>>>(h,  HID,   t1_W2, t1_b2, tbuf, DHALF, HID,   DHALF);
    // y1 = x1 * exp(tanh(spre)) + t2v  -> d_out cols [0,1024); logdet = rowsum
    ew_couple<<<BATCH, 256>>>(x, sbuf, tbuf, y, logdet, /*xColOff=*/0, /*yColOff=*/0, /*add=*/0);

    // --- Half 2: s1v = tanh(mlp_s2(y1)), t1v = mlp_t2(y1), y2 ---
    sgemm_bias<true ><<<gridH, blk>>>(y,  XCOLS, s2_W1, s2_b1, h,    HID,   DHALF, HID);
    sgemm_bias<false><<<gridD, blk>>>(h,  HID,   s2_W2, s2_b2, sbuf, DHALF, HID,   DHALF);
    sgemm_bias<true ><<<gridH, blk>>>(y,  XCOLS, t2_W1, t2_b1, h,    HID,   DHALF, HID);
    sgemm_bias<false><<<gridD, blk>>>(h,  HID,   t2_W2, t2_b2, tbuf, DHALF, HID,   DHALF);
    // y2 = x2 * exp(tanh(spre)) + t1v -> d_out cols [1024,2048); logdet += rowsum
    ew_couple<<<BATCH, 256>>>(x, sbuf, tbuf, y, logdet, /*xColOff=*/DHALF, /*yColOff=*/DHALF, /*add=*/1);
}

// round 3
// speedup vs baseline: 2.2591x; 2.2591x over previous
#include <cuda_runtime.h>
#include <cuda_bf16.h>
#include <cstdint>
#include <math.h>

#define BATCH 8192
#define DHALF 1024
#define HID   4096
#define XCOLS 2048
#define WSLOT ((size_t)DHALF * HID)

// ---------------- scratch (device globals: allocation-free rule) -----------
__device__ __nv_bfloat16 g_act_hi[(size_t)BATCH * DHALF];
__device__ __nv_bfloat16 g_act_lo[(size_t)BATCH * DHALF];
__device__ __nv_bfloat16 g_hid_hi[(size_t)BATCH * HID];
__device__ __nv_bfloat16 g_hid_lo[(size_t)BATCH * HID];
__device__ __nv_bfloat16 g_wt_hi[8 * WSLOT];
__device__ __nv_bfloat16 g_wt_lo[8 * WSLOT];
__device__ float g_s[(size_t)BATCH * DHALF];
__device__ float g_t[(size_t)BATCH * DHALF];

// ---------------- helpers ----------------------------------------------
__device__ __forceinline__ uint32_t smem_u32(const void* p) {
    uint32_t a;
    asm("{ .reg .u64 t; cvta.to.shared.u64 t, %1; cvt.u32.u64 %0, t; }" : "=r"(a) : "l"(p));
    return a;
}
__device__ __forceinline__ void cp16(uint32_t s, const void* g) {
    asm volatile("cp.async.cg.shared.global [%0], [%1], 16;" :: "r"(s), "l"(g));
}
__device__ __forceinline__ void split_bf(float v, __nv_bfloat16& hi, __nv_bfloat16& lo) {
    hi = __float2bfloat16(v);
    lo = __float2bfloat16(v - __bfloat162float(hi));
}
__device__ __forceinline__ uint32_t pack_bf2(__nv_bfloat16 a, __nv_bfloat16 b) {
    __nv_bfloat162 t = __halves2bfloat162(a, b);
    return *reinterpret_cast<uint32_t*>(&t);
}
__device__ __forceinline__ void mma16816(float* d, const uint32_t* a, const uint32_t* b) {
    asm volatile(
        "mma.sync.aligned.m16n8k16.row.col.f32.bf16.bf16.f32 "
        "{%0,%1,%2,%3}, {%4,%5,%6,%7}, {%8,%9}, {%0,%1,%2,%3};"
        : "+f"(d[0]), "+f"(d[1]), "+f"(d[2]), "+f"(d[3])
        : "r"(a[0]), "r"(a[1]), "r"(a[2]), "r"(a[3]), "r"(b[0]), "r"(b[1]));
}

// ---------------------------------------------------------------------------
// bf16x3 split GEMM on mma.sync: C[M,N] = A[M,K] @ WT[N,K]^T + bias.
// Block tile 128x128, BK=32, 3-stage cp.async pipeline, 8 warps (2m x 4n),
// warp tile 64x32. Smem rows padded to 40 bf16 (80B) -> conflict-free.
// ---------------------------------------------------------------------------
#define BM 128
#define BN 128
#define BK 32
#define STAGES 3
#define APITCH 80u                       // bytes per smem row
#define TILEB  (128u * APITCH)           // 10240 B per matrix tile
#define STAGEB (4u * TILEB)              // Ahi,Alo,Bhi,Blo
#define SMEM_BYTES (STAGES * STAGEB)     // 122880

template<bool RELU, bool BF16OUT>
__global__ __launch_bounds__(256, 1)
void gemm_mma_x3(const __nv_bfloat16* __restrict__ Ahi, const __nv_bfloat16* __restrict__ Alo,
                 const __nv_bfloat16* __restrict__ Bhi, const __nv_bfloat16* __restrict__ Blo,
                 const float* __restrict__ bias,
                 float* __restrict__ Cf,
                 __nv_bfloat16* __restrict__ Chi, __nv_bfloat16* __restrict__ Clo,
                 int K, int N)
{
    extern __shared__ char smem[];
    const uint32_t sb = smem_u32(smem);
    const int tid = threadIdx.x;
    const int wid = tid >> 5;
    const int lid = tid & 31;
    const int wm = wid & 1;          // 0..1 -> 64-row band
    const int wn = wid >> 1;         // 0..3 -> 32-col band
    const int mBase = blockIdx.y * BM;
    const int nBase = blockIdx.x * BN;

    // load mapping: 512 16B-chunks per matrix per stage; thread does 2 per matrix
    const int r0 = tid >> 1;                  // with j: r = (tid+256j)>>2 below
    (void)r0;

    auto load_stage = [&](int stage, int k0) {
        const uint32_t st = sb + stage * STAGEB;
        #pragma unroll
        for (int j = 0; j < 2; ++j) {
            int i = tid + 256 * j;            // 0..511
            int r = i >> 2, c = i & 3;        // row 0..127, chunk 0..3
            uint32_t off = (uint32_t)r * APITCH + (uint32_t)c * 16u;
            size_t ga = (size_t)(mBase + r) * K + k0 + c * 8;
            size_t gb = (size_t)(nBase + r) * K + k0 + c * 8;
            cp16(st + off,             Ahi + ga);
            cp16(st + TILEB + off,     Alo + ga);
            cp16(st + 2 * TILEB + off, Bhi + gb);
            cp16(st + 3 * TILEB + off, Blo + gb);
        }
        asm volatile("cp.async.commit_group;" ::: "memory");
    };

    float acc[4][4][4];
    #pragma unroll
    for (int i = 0; i < 4; ++i)
        #pragma unroll
        for (int j = 0; j < 4; ++j)
            #pragma unroll
            for (int q = 0; q < 4; ++q) acc[i][j][q] = 0.f;

    const int NC = K / BK;
    load_stage(0, 0);
    load_stage(1, BK);
    load_stage(2, 2 * BK);

    const int lr = lid >> 2;          // 0..7
    const int lc = (lid & 3) * 4;     // byte offset of 2-bf16 pair within 16B? -> (lid&3)*2 elems = *4 bytes

    for (int c = 0; c < NC; ++c) {
        const int s = c % STAGES;
        asm volatile("cp.async.wait_group %0;" :: "n"(STAGES - 1) : "memory");
        __syncthreads();

        const char* st   = smem + s * STAGEB;
        const char* AsH  = st;
        const char* AsL  = st + TILEB;
        const char* BsH  = st + 2 * TILEB;
        const char* BsL  = st + 3 * TILEB;

        #pragma unroll
        for (int k16 = 0; k16 < 2; ++k16) {
            const int kb = k16 * 16;
            uint32_t ah[4][4], al[4][4], bh[4][2], bl[4][2];

            #pragma unroll
            for (int mi = 0; mi < 4; ++mi) {
                int rr = wm * 64 + mi * 16 + lr;
                uint32_t o00 = (uint32_t)rr * APITCH + (kb * 2 + lc);
                uint32_t o10 = o00 + 8 * APITCH;
                ah[mi][0] = *(const uint32_t*)(AsH + o00);
                ah[mi][1] = *(const uint32_t*)(AsH + o10);
                ah[mi][2] = *(const uint32_t*)(AsH + o00 + 16);
                ah[mi][3] = *(const uint32_t*)(AsH + o10 + 16);
                al[mi][0] = *(const uint32_t*)(AsL + o00);
                al[mi][1] = *(const uint32_t*)(AsL + o10);
                al[mi][2] = *(const uint32_t*)(AsL + o00 + 16);
                al[mi][3] = *(const uint32_t*)(AsL + o10 + 16);
            }
            #pragma unroll
            for (int ni = 0; ni < 4; ++ni) {
                int nr = wn * 32 + ni * 8 + lr;
                uint32_t o0 = (uint32_t)nr * APITCH + (kb * 2 + lc);
                bh[ni][0] = *(const uint32_t*)(BsH + o0);
                bh[ni][1] = *(const uint32_t*)(BsH + o0 + 16);
                bl[ni][0] = *(const uint32_t*)(BsL + o0);
                bl[ni][1] = *(const uint32_t*)(BsL + o0 + 16);
            }

            #pragma unroll
            for (int mi = 0; mi < 4; ++mi)
                #pragma unroll
                for (int ni = 0; ni < 4; ++ni)
                    mma16816(acc[mi][ni], ah[mi], bh[ni]);
            #pragma unroll
            for (int mi = 0; mi < 4; ++mi)
                #pragma unroll
                for (int ni = 0; ni < 4; ++ni)
                    mma16816(acc[mi][ni], ah[mi], bl[ni]);
            #pragma unroll
            for (int mi = 0; mi < 4; ++mi)
                #pragma unroll
                for (int ni = 0; ni < 4; ++ni)
                    mma16816(acc[mi][ni], al[mi], bh[ni]);
        }

        __syncthreads();
        if (c + STAGES < NC) load_stage(s, (c + STAGES) * BK);
    }

    // ---- epilogue ----
    const int q2 = (lid & 3) * 2;
    #pragma unroll
    for (int mi = 0; mi < 4; ++mi) {
        #pragma unroll
        for (int half = 0; half < 2; ++half) {       // row and row+8
            const int m = mBase + wm * 64 + mi * 16 + lr + half * 8;
            #pragma unroll
            for (int ni = 0; ni < 4; ++ni) {
                const int n = nBase + wn * 32 + ni * 8 + q2;
                float v0 = acc[mi][ni][half * 2 + 0] + bias[n];
                float v1 = acc[mi][ni][half * 2 + 1] + bias[n + 1];
                if (RELU) { v0 = fmaxf(v0, 0.f); v1 = fmaxf(v1, 0.f); }
                if (BF16OUT) {
                    __nv_bfloat16 h0, h1, l0, l1;
                    split_bf(v0, h0, l0);
                    split_bf(v1, h1, l1);
                    *reinterpret_cast<uint32_t*>(&Chi[(size_t)m * N + n]) = pack_bf2(h0, h1);
                    *reinterpret_cast<uint32_t*>(&Clo[(size_t)m * N + n]) = pack_bf2(l0, l1);
                } else {
                    *reinterpret_cast<float2*>(&Cf[(size_t)m * N + n]) = make_float2(v0, v1);
                }
            }
        }
    }
}

// ---------------------------------------------------------------------------
// Weight converter: W[K,N] fp32 -> WT[N,K] bf16 hi/lo (transpose + split)
// ---------------------------------------------------------------------------
__global__ __launch_bounds__(256)
void convert_wT(const float* __restrict__ W,
                __nv_bfloat16* __restrict__ Thi, __nv_bfloat16* __restrict__ Tlo,
                int K, int N)
{
    __shared__ float t[32][33];
    const int n0 = blockIdx.x * 32, k0 = blockIdx.y * 32;
    const int tx = threadIdx.x & 31, ty = threadIdx.x >> 5;
    #pragma unroll
    for (int i = 0; i < 4; ++i)
        t[ty + i * 8][tx] = W[(size_t)(k0 + ty + i * 8) * N + n0 + tx];
    __syncthreads();
    #pragma unroll
    for (int i = 0; i < 4; ++i) {
        int n = n0 + ty + i * 8;
        float v = t[tx][ty + i * 8];
        __nv_bfloat16 hi, lo;
        split_bf(v, hi, lo);
        Thi[(size_t)n * K + k0 + tx] = hi;
        Tlo[(size_t)n * K + k0 + tx] = lo;
    }
}

__global__ __launch_bounds__(256)
void convert_act(const float* __restrict__ x,
                 __nv_bfloat16* __restrict__ hi, __nv_bfloat16* __restrict__ lo)
{
    const int m = blockIdx.x;
    const int j = threadIdx.x * 4;
    float4 v = *reinterpret_cast<const float4*>(&x[(size_t)m * XCOLS + DHALF + j]);
    __nv_bfloat16 h0, h1, h2, h3, l0, l1, l2, l3;
    split_bf(v.x, h0, l0); split_bf(v.y, h1, l1);
    split_bf(v.z, h2, l2); split_bf(v.w, h3, l3);
    *reinterpret_cast<uint2*>(&hi[(size_t)m * DHALF + j]) = make_uint2(pack_bf2(h0, h1), pack_bf2(h2, h3));
    *reinterpret_cast<uint2*>(&lo[(size_t)m * DHALF + j]) = make_uint2(pack_bf2(l0, l1), pack_bf2(l2, l3));
}

// ---------------------------------------------------------------------------
// Coupling epilogue (fused y write, logdet, optional bf16 split of y half)
// ---------------------------------------------------------------------------
__global__ __launch_bounds__(256)
void ew_couple(const float* __restrict__ x,
               const float* __restrict__ spre,
               const float* __restrict__ tval,
               float* __restrict__ y,
               float* __restrict__ logdet,
               __nv_bfloat16* __restrict__ acthi, __nv_bfloat16* __restrict__ actlo,
               int xColOff, int yColOff, int addLogdet, int writeAct)
{
    const int m = blockIdx.x;
    const int j = threadIdx.x * 4;

    float4 sp = *reinterpret_cast<const float4*>(&spre[(size_t)m * DHALF + j]);
    float4 tv = *reinterpret_cast<const float4*>(&tval[(size_t)m * DHALF + j]);
    float4 xv = *reinterpret_cast<const float4*>(&x[(size_t)m * XCOLS + xColOff + j]);

    float s0 = tanhf(sp.x), s1 = tanhf(sp.y), s2 = tanhf(sp.z), s3 = tanhf(sp.w);

    float4 o;
    o.x = xv.x * expf(s0) + tv.x;
    o.y = xv.y * expf(s1) + tv.y;
    o.z = xv.z * expf(s2) + tv.z;
    o.w = xv.w * expf(s3) + tv.w;
    *reinterpret_cast<float4*>(&y[(size_t)m * XCOLS + yColOff + j]) = o;

    if (writeAct) {
        __nv_bfloat16 h0, h1, h2, h3, l0, l1, l2, l3;
        split_bf(o.x, h0, l0); split_bf(o.y, h1, l1);
        split_bf(o.z, h2, l2); split_bf(o.w, h3, l3);
        *reinterpret_cast<uint2*>(&acthi[(size_t)m * DHALF + j]) = make_uint2(pack_bf2(h0, h1), pack_bf2(h2, h3));
        *reinterpret_cast<uint2*>(&actlo[(size_t)m * DHALF + j]) = make_uint2(pack_bf2(l0, l1), pack_bf2(l2, l3));
    }

    float lsum = s0 + s1 + s2 + s3;
    #pragma unroll
    for (int off = 16; off > 0; off >>= 1)
        lsum += __shfl_xor_sync(0xFFFFFFFFu, lsum, off);

    __shared__ float wsum[8];
    if ((threadIdx.x & 31) == 0) wsum[threadIdx.x >> 5] = lsum;
    __syncthreads();
    if (threadIdx.x == 0) {
        float tot = 0.0f;
        #pragma unroll
        for (int w = 0; w < 8; ++w) tot += wsum[w];
        if (addLogdet) logdet[m] += tot;
        else           logdet[m]  = tot;
    }
}

// ---------------------------------------------------------------------------
extern "C" void kernel_launch(void* const* d_in, const int* in_sizes, int n_in,
                              void* d_out, int out_size)
{
    (void)in_sizes; (void)n_in; (void)out_size;

    const float* x = (const float*)d_in[0];
    const float* W[8] = { (const float*)d_in[1],  (const float*)d_in[3],
                          (const float*)d_in[5],  (const float*)d_in[7],
                          (const float*)d_in[9],  (const float*)d_in[11],
                          (const float*)d_in[13], (const float*)d_in[15] };
    const float* B[8] = { (const float*)d_in[2],  (const float*)d_in[4],
                          (const float*)d_in[6],  (const float*)d_in[8],
                          (const float*)d_in[10], (const float*)d_in[12],
                          (const float*)d_in[14], (const float*)d_in[16] };

    float* y      = (float*)d_out;
    float* logdet = y + (size_t)BATCH * XCOLS;

    __nv_bfloat16 *acthi, *actlo, *hidhi, *hidlo, *wthi, *wtlo;
    float *sbuf, *tbuf;
    cudaGetSymbolAddress((void**)&acthi, g_act_hi);
    cudaGetSymbolAddress((void**)&actlo, g_act_lo);
    cudaGetSymbolAddress((void**)&hidhi, g_hid_hi);
    cudaGetSymbolAddress((void**)&hidlo, g_hid_lo);
    cudaGetSymbolAddress((void**)&wthi,  g_wt_hi);
    cudaGetSymbolAddress((void**)&wtlo,  g_wt_lo);
    cudaGetSymbolAddress((void**)&sbuf,  g_s);
    cudaGetSymbolAddress((void**)&tbuf,  g_t);

    cudaFuncSetAttribute(gemm_mma_x3<true,  true >, cudaFuncAttributeMaxDynamicSharedMemorySize, SMEM_BYTES);
    cudaFuncSetAttribute(gemm_mma_x3<false, false>, cudaFuncAttributeMaxDynamicSharedMemorySize, SMEM_BYTES);

    // converters: i even -> W1 (K=1024,N=4096); i odd -> W2 (K=4096,N=1024)
    for (int i = 0; i < 8; ++i) {
        int K = (i & 1) ? HID : DHALF;
        int N = (i & 1) ? DHALF : HID;
        convert_wT<<<dim3(N / 32, K / 32), 256>>>(W[i], wthi + (size_t)i * WSLOT, wtlo + (size_t)i * WSLOT, K, N);
    }
    convert_act<<<BATCH, 256>>>(x, acthi, actlo);

    dim3 blk(256);
    dim3 gridH(HID / BN,   BATCH / BM);
    dim3 gridD(DHALF / BN, BATCH / BM);

    // phase 1
    gemm_mma_x3<true,  true ><<<gridH, blk, SMEM_BYTES>>>(acthi, actlo, wthi + 0 * WSLOT, wtlo + 0 * WSLOT, B[0], nullptr, hidhi, hidlo, DHALF, HID);
    gemm_mma_x3<false, false><<<gridD, blk, SMEM_BYTES>>>(hidhi, hidlo, wthi + 1 * WSLOT, wtlo + 1 * WSLOT, B[1], sbuf,    nullptr, nullptr, HID, DHALF);
    gemm_mma_x3<true,  true ><<<gridH, blk, SMEM_BYTES>>>(acthi, actlo, wthi + 2 * WSLOT, wtlo + 2 * WSLOT, B[2], nullptr, hidhi, hidlo, DHALF, HID);
    gemm_mma_x3<false, false><<<gridD, blk, SMEM_BYTES>>>(hidhi, hidlo, wthi + 3 * WSLOT, wtlo + 3 * WSLOT, B[3], tbuf,    nullptr, nullptr, HID, DHALF);
    ew_couple<<<BATCH, 256>>>(x, sbuf, tbuf, y, logdet, acthi, actlo, 0, 0, 0, 1);

    // phase 2
    gemm_mma_x3<true,  true ><<<gridH, blk, SMEM_BYTES>>>(acthi, actlo, wthi + 4 * WSLOT, wtlo + 4 * WSLOT, B[4], nullptr, hidhi, hidlo, DHALF, HID);
    gemm_mma_x3<false, false><<<gridD, blk, SMEM_BYTES>>>(hidhi, hidlo, wthi + 5 * WSLOT, wtlo + 5 * WSLOT, B[5], sbuf,    nullptr, nullptr, HID, DHALF);
    gemm_mma_x3<true,  true ><<<gridH, blk, SMEM_BYTES>>>(acthi, actlo, wthi + 6 * WSLOT, wtlo + 6 * WSLOT, B[6], nullptr, hidhi, hidlo, DHALF, HID);
    gemm_mma_x3<false, false><<<gridD, blk, SMEM_BYTES>>>(hidhi, hidlo, wthi + 7 * WSLOT, wtlo + 7 * WSLOT, B[7], tbuf,    nullptr, nullptr, HID, DHALF);
    ew_couple<<<BATCH, 256>>>(x, sbuf, tbuf, y, logdet, nullptr, nullptr, DHALF, DHALF, 1, 0);
}